// round 2
// baseline (speedup 1.0000x reference)
#include <cuda_runtime.h>
#include <math.h>

#define B 16
#define T 2048
#define F 128
#define U 256

// Scratch for sigmoid'd projections (device globals: allocation-free rule)
__device__ float g_q[B * T * U];
__device__ float g_v[B * T * U];
__device__ float g_k[B * T * U];

#define XS_STRIDE 132   // 64 x 128 x-tile, padded (33 odd 16B units)
#define WS_STRIDE 68    // 128 x 64 W-tile, padded (17 odd)
#define QS 260          // 64 x 256 tiles, padded (65 odd)
#define PSS 68          // 64 x 64 P tile, padded (17 odd)

#define NEG_BIG (-1e30f)

// ---------------------------------------------------------------------------
// Kernel 1: out = sigmoid(x @ W) for W in {Wq, Wv, Wk} -> g_q/g_v/g_k
// grid (BT/64, U/64, 3), block 256 (16x16 threads, 4x4 microtile)
// ---------------------------------------------------------------------------
__global__ __launch_bounds__(256) void proj_kernel(
    const float* __restrict__ x,
    const float* __restrict__ Wq,
    const float* __restrict__ Wv,
    const float* __restrict__ Wk)
{
    extern __shared__ float sm[];
    float* Xs = sm;                      // 64 x XS_STRIDE
    float* Ws = sm + 64 * XS_STRIDE;     // 128 x WS_STRIDE

    const int tid = threadIdx.x;
    const int ty = tid >> 4;
    const int tx = tid & 15;
    const int rb = blockIdx.x * 64;      // row base within B*T
    const int cb = blockIdx.y * 64;      // col base within U

    const float* W  = (blockIdx.z == 0) ? Wq : (blockIdx.z == 1) ? Wv : Wk;
    float*       Out = (blockIdx.z == 0) ? g_q : (blockIdx.z == 1) ? g_v : g_k;

    // Load X tile: 64 x 128 floats = 2048 float4
    #pragma unroll
    for (int it = 0; it < 8; it++) {
        int idx = tid + it * 256;
        int r = idx >> 5, c4 = idx & 31;
        *(float4*)&Xs[r * XS_STRIDE + c4 * 4] =
            *(const float4*)&x[(size_t)(rb + r) * F + c4 * 4];
    }
    // Load W tile: 128 x 64 floats = 2048 float4
    #pragma unroll
    for (int it = 0; it < 8; it++) {
        int idx = tid + it * 256;
        int f = idx >> 4, c4 = idx & 15;
        *(float4*)&Ws[f * WS_STRIDE + c4 * 4] =
            *(const float4*)&W[(size_t)f * U + cb + c4 * 4];
    }
    __syncthreads();

    float acc[4][4];
    #pragma unroll
    for (int i = 0; i < 4; i++)
        #pragma unroll
        for (int j = 0; j < 4; j++) acc[i][j] = 0.f;

    #pragma unroll
    for (int kk = 0; kk < F; kk += 4) {
        float xr[4][4], wr[4][4];
        #pragma unroll
        for (int i = 0; i < 4; i++)
            *(float4*)&xr[i][0] = *(const float4*)&Xs[(ty * 4 + i) * XS_STRIDE + kk];
        #pragma unroll
        for (int p = 0; p < 4; p++)
            *(float4*)&wr[p][0] = *(const float4*)&Ws[(kk + p) * WS_STRIDE + tx * 4];
        #pragma unroll
        for (int i = 0; i < 4; i++)
            #pragma unroll
            for (int j = 0; j < 4; j++)
                #pragma unroll
                for (int p = 0; p < 4; p++)
                    acc[i][j] = fmaf(xr[i][p], wr[p][j], acc[i][j]);
    }

    #pragma unroll
    for (int i = 0; i < 4; i++) {
        float4 o;
        float* op = (float*)&o;
        #pragma unroll
        for (int j = 0; j < 4; j++)
            op[j] = 1.f / (1.f + __expf(-acc[i][j]));
        *(float4*)&Out[(size_t)(rb + ty * 4 + i) * U + cb + tx * 4] = o;
    }
}

// ---------------------------------------------------------------------------
// Kernel 2: flash attention, strictly-causal (s < t), scale 1/sqrt(F).
// "keys" = g_v (score = q.v^T), "values" = g_k (context = P.k).
// grid (32, B): one 64-query-row tile per block; block 256 threads.
// ---------------------------------------------------------------------------
__global__ __launch_bounds__(256) void attn_kernel(float* __restrict__ out)
{
    extern __shared__ float sm[];
    float* Qs = sm;                 // 64 x QS
    float* Vs = Qs + 64 * QS;       // 64 x QS (key tile)
    float* Ks = Vs + 64 * QS;       // 64 x QS (value tile)
    float* Ps = Ks + 64 * QS;       // 64 x PSS

    const int tid = threadIdx.x;
    const int ty = tid >> 4;
    const int tx = tid & 15;
    const int qt = 31 - (int)blockIdx.x;   // big tiles launch first
    const int b  = blockIdx.y;
    const int t0 = qt * 64;

    const float* qb = g_q + (size_t)b * T * U;
    const float* vb = g_v + (size_t)b * T * U;
    const float* kb = g_k + (size_t)b * T * U;

    // Load Q tile (64 x 256 = 4096 float4)
    #pragma unroll
    for (int it = 0; it < 16; it++) {
        int idx = tid + it * 256;
        int r = idx >> 6, c4 = idx & 63;
        *(float4*)&Qs[r * QS + c4 * 4] =
            *(const float4*)&qb[(size_t)(t0 + r) * U + c4 * 4];
    }

    float m[4], l[4];
    float4 O[4][4];
    #pragma unroll
    for (int i = 0; i < 4; i++) {
        m[i] = NEG_BIG; l[i] = 0.f;
        #pragma unroll
        for (int n = 0; n < 4; n++) O[i][n] = make_float4(0.f, 0.f, 0.f, 0.f);
    }

    const float scale = 0.0883883476483184405f;  // 1/sqrt(128)

    for (int j = 0; j <= qt; j++) {
        __syncthreads();  // previous O-GEMM readers done with Vs/Ks/Ps (and Qs visible on j=0)
        const int s0 = j * 64;
        #pragma unroll
        for (int it = 0; it < 16; it++) {
            int idx = tid + it * 256;
            int r = idx >> 6, c4 = idx & 63;
            *(float4*)&Vs[r * QS + c4 * 4] =
                *(const float4*)&vb[(size_t)(s0 + r) * U + c4 * 4];
            *(float4*)&Ks[r * QS + c4 * 4] =
                *(const float4*)&kb[(size_t)(s0 + r) * U + c4 * 4];
        }
        __syncthreads();

        // S[4][4]: rows ty*4+i, cols jj*16+tx (within key tile)
        float S[4][4];
        #pragma unroll
        for (int i = 0; i < 4; i++)
            #pragma unroll
            for (int jj = 0; jj < 4; jj++) S[i][jj] = 0.f;

        #pragma unroll 4
        for (int kk = 0; kk < U; kk += 4) {
            float xr[4][4], vr[4][4];
            #pragma unroll
            for (int i = 0; i < 4; i++)
                *(float4*)&xr[i][0] = *(const float4*)&Qs[(ty * 4 + i) * QS + kk];
            #pragma unroll
            for (int jj = 0; jj < 4; jj++)
                *(float4*)&vr[jj][0] = *(const float4*)&Vs[(jj * 16 + tx) * QS + kk];
            #pragma unroll
            for (int i = 0; i < 4; i++)
                #pragma unroll
                for (int jj = 0; jj < 4; jj++)
                    #pragma unroll
                    for (int p = 0; p < 4; p++)
                        S[i][jj] = fmaf(xr[i][p], vr[jj][p], S[i][jj]);
        }

        // scale + strictly-causal mask + online softmax update
        float tmax[4];
        #pragma unroll
        for (int i = 0; i < 4; i++) {
            const int t = t0 + ty * 4 + i;
            float mx = NEG_BIG;
            #pragma unroll
            for (int jj = 0; jj < 4; jj++) {
                const int s = s0 + jj * 16 + tx;
                float v = S[i][jj] * scale;
                if (s >= t) v = NEG_BIG;
                S[i][jj] = v;
                mx = fmaxf(mx, v);
            }
            tmax[i] = mx;
        }
        #pragma unroll
        for (int msk = 8; msk; msk >>= 1)
            #pragma unroll
            for (int i = 0; i < 4; i++)
                tmax[i] = fmaxf(tmax[i], __shfl_xor_sync(0xffffffffu, tmax[i], msk));

        float cf[4], rs[4];
        #pragma unroll
        for (int i = 0; i < 4; i++) {
            float mn = fmaxf(m[i], tmax[i]);
            cf[i] = __expf(m[i] - mn);
            m[i] = mn;
            float sum = 0.f;
            #pragma unroll
            for (int jj = 0; jj < 4; jj++) {
                float p = __expf(S[i][jj] - mn);
                S[i][jj] = p;
                sum += p;
            }
            rs[i] = sum;
        }
        #pragma unroll
        for (int msk = 8; msk; msk >>= 1)
            #pragma unroll
            for (int i = 0; i < 4; i++)
                rs[i] += __shfl_xor_sync(0xffffffffu, rs[i], msk);
        #pragma unroll
        for (int i = 0; i < 4; i++) l[i] = l[i] * cf[i] + rs[i];

        // stash probabilities, rescale accumulator
        #pragma unroll
        for (int i = 0; i < 4; i++)
            #pragma unroll
            for (int jj = 0; jj < 4; jj++)
                Ps[(ty * 4 + i) * PSS + jj * 16 + tx] = S[i][jj];
        #pragma unroll
        for (int i = 0; i < 4; i++) {
            #pragma unroll
            for (int n = 0; n < 4; n++) {
                O[i][n].x *= cf[i]; O[i][n].y *= cf[i];
                O[i][n].z *= cf[i]; O[i][n].w *= cf[i];
            }
        }
        __syncthreads();

        // O += P @ K  (rows ty*4+i, dims n*64 + tx*4)
        #pragma unroll 2
        for (int c = 0; c < 64; c++) {
            float p[4];
            #pragma unroll
            for (int i = 0; i < 4; i++) p[i] = Ps[(ty * 4 + i) * PSS + c];
            float4 kv[4];
            #pragma unroll
            for (int n = 0; n < 4; n++)
                kv[n] = *(const float4*)&Ks[c * QS + n * 64 + tx * 4];
            #pragma unroll
            for (int i = 0; i < 4; i++)
                #pragma unroll
                for (int n = 0; n < 4; n++) {
                    O[i][n].x = fmaf(p[i], kv[n].x, O[i][n].x);
                    O[i][n].y = fmaf(p[i], kv[n].y, O[i][n].y);
                    O[i][n].z = fmaf(p[i], kv[n].z, O[i][n].z);
                    O[i][n].w = fmaf(p[i], kv[n].w, O[i][n].w);
                }
        }
    }

    // epilogue: normalize; global row t==0 forced to zeros
    #pragma unroll
    for (int i = 0; i < 4; i++) {
        const int t = t0 + ty * 4 + i;
        const float inv = 1.f / l[i];
        #pragma unroll
        for (int n = 0; n < 4; n++) {
            float4 o = O[i][n];
            o.x *= inv; o.y *= inv; o.z *= inv; o.w *= inv;
            if (t == 0) o = make_float4(0.f, 0.f, 0.f, 0.f);
            *(float4*)&out[((size_t)b * T + t) * U + n * 64 + tx * 4] = o;
        }
    }
}

// ---------------------------------------------------------------------------
extern "C" void kernel_launch(void* const* d_in, const int* in_sizes, int n_in,
                              void* d_out, int out_size)
{
    const float* x  = (const float*)d_in[0];
    const float* Wq = (const float*)d_in[1];
    const float* Wv = (const float*)d_in[2];
    const float* Wk = (const float*)d_in[3];
    float* out = (float*)d_out;

    const int smem1 = (64 * XS_STRIDE + 128 * WS_STRIDE) * 4;   // 68,608 B
    const int smem2 = (3 * 64 * QS + 64 * PSS) * 4;             // 217,088 B
    cudaFuncSetAttribute(proj_kernel, cudaFuncAttributeMaxDynamicSharedMemorySize, smem1);
    cudaFuncSetAttribute(attn_kernel, cudaFuncAttributeMaxDynamicSharedMemorySize, smem2);

    dim3 g1((B * T) / 64, U / 64, 3);
    proj_kernel<<<g1, 256, smem1>>>(x, Wq, Wv, Wk);

    dim3 g2(T / 64, B);
    attn_kernel<<<g2, 256, smem2>>>(out);
}

// round 4
// speedup vs baseline: 2.4941x; 2.4941x over previous
#include <cuda_runtime.h>
#include <stdint.h>

#define NBAT 16
#define NT 2048
#define NF 128
#define NU 256
#define NBT (NBAT*NT)

__device__ float g_q[NBT*NU];
__device__ float g_v[NBT*NU];
__device__ float g_k[NBT*NU];

#define XSTR 132   // proj X tile stride (mod 32 banks = 4)
#define WSTR 264   // proj W tile stride (mod 32 banks = 8)
#define QSTR 260   // attn Q tile stride (=4)
#define VSTR 260   // attn V tile stride (=4)
#define KSTR 264   // attn K tile stride (=8)

__device__ __forceinline__ uint32_t f2tf(float f){
    uint32_t r; asm("cvt.rna.tf32.f32 %0, %1;" : "=r"(r) : "f"(f)); return r;
}
__device__ __forceinline__ float ex2(float x){
    float r; asm("ex2.approx.f32 %0, %1;" : "=f"(r) : "f"(x)); return r;
}
__device__ __forceinline__ void mma8(float* d, uint32_t a0, uint32_t a1,
                                     uint32_t a2, uint32_t a3,
                                     uint32_t b0, uint32_t b1){
    asm volatile(
        "mma.sync.aligned.m16n8k8.row.col.f32.tf32.tf32.f32 "
        "{%0,%1,%2,%3}, {%4,%5,%6,%7}, {%8,%9}, {%0,%1,%2,%3};"
        : "+f"(d[0]), "+f"(d[1]), "+f"(d[2]), "+f"(d[3])
        : "r"(a0), "r"(a1), "r"(a2), "r"(a3), "r"(b0), "r"(b1));
}
__device__ __forceinline__ float sigmoidf(float x){
    return 1.f / (1.f + __expf(-x));
}

// ---------------------------------------------------------------------------
// Kernel 1: q/v/k = round_tf32(sigmoid(x @ W)). One 128x256 tile per CTA.
// grid (BT/128, 3), block 256 (8 warps, warp owns 16 rows x 256 cols).
// ---------------------------------------------------------------------------
__global__ __launch_bounds__(256, 1) void proj_kernel(
    const float* __restrict__ x,  const float* __restrict__ Wq,
    const float* __restrict__ Wv, const float* __restrict__ Wk)
{
    extern __shared__ float sm[];
    float* Xs = sm;                 // 128 x XSTR
    float* Ws = sm + 128 * XSTR;    // 128 x WSTR  (rows = f, cols = u)

    const int tid = threadIdx.x, w = tid >> 5, lane = tid & 31;
    const int g = lane >> 2, q = lane & 3;
    const int rb = blockIdx.x * 128, z = blockIdx.y;
    const float* W  = (z == 0) ? Wq : (z == 1) ? Wv : Wk;
    float*      Out = (z == 0) ? g_q : (z == 1) ? g_v : g_k;

    // X tile [128 x 128], rounded to tf32
    #pragma unroll
    for (int i = 0; i < 16; i++){
        int idx = tid + i * 256; int r = idx >> 5, c4 = idx & 31;
        float4 v = *(const float4*)&x[(size_t)(rb + r) * NF + c4 * 4];
        float* d = &Xs[r * XSTR + c4 * 4];
        d[0] = __uint_as_float(f2tf(v.x)); d[1] = __uint_as_float(f2tf(v.y));
        d[2] = __uint_as_float(f2tf(v.z)); d[3] = __uint_as_float(f2tf(v.w));
    }
    // W tile [128 x 256], rounded to tf32
    #pragma unroll
    for (int i = 0; i < 32; i++){
        int idx = tid + i * 256; int r = idx >> 6, c4 = idx & 63;
        float4 v = *(const float4*)&W[(size_t)r * NU + c4 * 4];
        float* d = &Ws[r * WSTR + c4 * 4];
        d[0] = __uint_as_float(f2tf(v.x)); d[1] = __uint_as_float(f2tf(v.y));
        d[2] = __uint_as_float(f2tf(v.z)); d[3] = __uint_as_float(f2tf(v.w));
    }
    __syncthreads();

    float acc[32][4];
    #pragma unroll
    for (int nb = 0; nb < 32; nb++)
        #pragma unroll
        for (int e = 0; e < 4; e++) acc[nb][e] = 0.f;

    const float* Qw = Xs + (w * 16) * XSTR;
    #pragma unroll 4
    for (int kb = 0; kb < 16; kb++){
        const int k0 = kb * 8;
        uint32_t a0 = __float_as_uint(Qw[g * XSTR + k0 + q]);
        uint32_t a1 = __float_as_uint(Qw[(g + 8) * XSTR + k0 + q]);
        uint32_t a2 = __float_as_uint(Qw[g * XSTR + k0 + q + 4]);
        uint32_t a3 = __float_as_uint(Qw[(g + 8) * XSTR + k0 + q + 4]);
        #pragma unroll
        for (int nb = 0; nb < 32; nb++){
            uint32_t b0 = __float_as_uint(Ws[(k0 + q) * WSTR + nb * 8 + g]);
            uint32_t b1 = __float_as_uint(Ws[(k0 + q + 4) * WSTR + nb * 8 + g]);
            mma8(acc[nb], a0, a1, a2, a3, b0, b1);
        }
    }

    const int r0 = rb + w * 16 + g, r1 = r0 + 8;
    #pragma unroll
    for (int nb = 0; nb < 32; nb++){
        int c = nb * 8 + 2 * q;
        float2 v0, v1;
        v0.x = __uint_as_float(f2tf(sigmoidf(acc[nb][0])));
        v0.y = __uint_as_float(f2tf(sigmoidf(acc[nb][1])));
        v1.x = __uint_as_float(f2tf(sigmoidf(acc[nb][2])));
        v1.y = __uint_as_float(f2tf(sigmoidf(acc[nb][3])));
        *(float2*)&Out[(size_t)r0 * NU + c] = v0;
        *(float2*)&Out[(size_t)r1 * NU + c] = v1;
    }
}

// ---------------------------------------------------------------------------
// Kernel 2: flash attention via mma.sync tf32. Static softmax max (q,v in
// (0,1) => score <= 256/sqrt(128)), so no online rescaling; O and l live in
// registers for the whole key loop. V and K share one smem buffer.
// grid (16 qtiles, 16 batches), block 256.
// ---------------------------------------------------------------------------
__global__ __launch_bounds__(256, 1) void attn_kernel(float* __restrict__ out)
{
    extern __shared__ float sm[];
    float* Qs = sm;                  // 128 x QSTR
    float* VK = sm + 128 * QSTR;     // 64 x VSTR  /  64 x KSTR (shared)

    const int tid = threadIdx.x, w = tid >> 5, lane = tid & 31;
    const int g = lane >> 2, q = lane & 3;
    const int qt = 15 - (int)blockIdx.x;      // big tiles first
    const int b  = blockIdx.y;
    const int t0 = qt * 128;
    const int srow0 = t0 + w * 16 + g, srow1 = srow0 + 8;

    const float* qb = g_q + (size_t)(b * NT) * NU;
    const float* vb = g_v + (size_t)(b * NT) * NU;
    const float* kb = g_k + (size_t)(b * NT) * NU;

    // Q tile [128 x 256] (values already tf32-rounded by proj)
    #pragma unroll
    for (int i = 0; i < 32; i++){
        int idx = tid + i * 256; int r = idx >> 6, c4 = idx & 63;
        *(float4*)&Qs[r * QSTR + c4 * 4] =
            *(const float4*)&qb[(size_t)(t0 + r) * NU + c4 * 4];
    }

    float oacc[32][4];
    #pragma unroll
    for (int nb = 0; nb < 32; nb++)
        #pragma unroll
        for (int e = 0; e < 4; e++) oacc[nb][e] = 0.f;
    float l0 = 0.f, l1 = 0.f;

    const float C1 = 0.127517906167328651f;   // (1/sqrt(128)) * log2(e)
    const float C2 = 32.6444645f;             // 22.627417 * log2(e) (static max)

    const int jn = 2 * qt + 2;
    for (int j = 0; j < jn; j++){
        const int s0 = j * 64;
        __syncthreads();                       // prev O-GEMM done with buffer
        #pragma unroll
        for (int i = 0; i < 16; i++){
            int idx = tid + i * 256; int r = idx >> 6, c4 = idx & 63;
            *(float4*)&VK[r * VSTR + c4 * 4] =
                *(const float4*)&vb[(size_t)(s0 + r) * NU + c4 * 4];
        }
        __syncthreads();

        // ---- S = Q . V^T  (warp: 16 rows x 64 cols) ----
        float sacc[8][4];
        #pragma unroll
        for (int nb = 0; nb < 8; nb++)
            #pragma unroll
            for (int e = 0; e < 4; e++) sacc[nb][e] = 0.f;

        const float* Qw = Qs + (w * 16) * QSTR;
        #pragma unroll 4
        for (int kc = 0; kc < 32; kc++){
            const int k0 = kc * 8;
            uint32_t a0 = __float_as_uint(Qw[g * QSTR + k0 + q]);
            uint32_t a1 = __float_as_uint(Qw[(g + 8) * QSTR + k0 + q]);
            uint32_t a2 = __float_as_uint(Qw[g * QSTR + k0 + q + 4]);
            uint32_t a3 = __float_as_uint(Qw[(g + 8) * QSTR + k0 + q + 4]);
            #pragma unroll
            for (int nb = 0; nb < 8; nb++){
                uint32_t b0 = __float_as_uint(VK[(nb * 8 + g) * VSTR + k0 + q]);
                uint32_t b1 = __float_as_uint(VK[(nb * 8 + g) * VSTR + k0 + q + 4]);
                mma8(sacc[nb], a0, a1, a2, a3, b0, b1);
            }
        }

        // ---- softmax (static max), l accumulation ----
        float pl0 = 0.f, pl1 = 0.f;
        #pragma unroll
        for (int nb = 0; nb < 8; nb++){
            int c0 = s0 + nb * 8 + 2 * q;
            float p0 = (c0     < srow0) ? ex2(fmaf(sacc[nb][0], C1, -C2)) : 0.f;
            float p1 = (c0 + 1 < srow0) ? ex2(fmaf(sacc[nb][1], C1, -C2)) : 0.f;
            float p2 = (c0     < srow1) ? ex2(fmaf(sacc[nb][2], C1, -C2)) : 0.f;
            float p3 = (c0 + 1 < srow1) ? ex2(fmaf(sacc[nb][3], C1, -C2)) : 0.f;
            pl0 += p0 + p1; pl1 += p2 + p3;
            sacc[nb][0] = p0; sacc[nb][1] = p1;
            sacc[nb][2] = p2; sacc[nb][3] = p3;
        }
        pl0 += __shfl_xor_sync(~0u, pl0, 1); pl0 += __shfl_xor_sync(~0u, pl0, 2);
        pl1 += __shfl_xor_sync(~0u, pl1, 1); pl1 += __shfl_xor_sync(~0u, pl1, 2);
        l0 += pl0; l1 += pl1;

        // ---- C-frag -> A-frag conversion of P via shuffles ----
        uint32_t pa[8][4];
        const int base = lane & ~3;
        const int src0 = base + (q >> 1), src1 = src0 + 2;
        const bool odd = q & 1;
        #pragma unroll
        for (int kc = 0; kc < 8; kc++){
            float x0 = __shfl_sync(~0u, sacc[kc][0], src0);
            float x1 = __shfl_sync(~0u, sacc[kc][1], src0);
            float x2 = __shfl_sync(~0u, sacc[kc][2], src0);
            float x3 = __shfl_sync(~0u, sacc[kc][3], src0);
            float y0 = __shfl_sync(~0u, sacc[kc][0], src1);
            float y1 = __shfl_sync(~0u, sacc[kc][1], src1);
            float y2 = __shfl_sync(~0u, sacc[kc][2], src1);
            float y3 = __shfl_sync(~0u, sacc[kc][3], src1);
            pa[kc][0] = __float_as_uint(odd ? x1 : x0);
            pa[kc][1] = __float_as_uint(odd ? x3 : x2);
            pa[kc][2] = __float_as_uint(odd ? y1 : y0);
            pa[kc][3] = __float_as_uint(odd ? y3 : y2);
        }

        __syncthreads();                       // all warps done reading V
        #pragma unroll
        for (int i = 0; i < 16; i++){
            int idx = tid + i * 256; int r = idx >> 6, c4 = idx & 63;
            *(float4*)&VK[r * KSTR + c4 * 4] =
                *(const float4*)&kb[(size_t)(s0 + r) * NU + c4 * 4];
        }
        __syncthreads();

        // ---- O += P . K  (warp: 16 rows x 256 cols) ----
        #pragma unroll
        for (int kc = 0; kc < 8; kc++){
            #pragma unroll
            for (int nb = 0; nb < 32; nb++){
                uint32_t b0 = __float_as_uint(VK[(kc * 8 + q) * KSTR + nb * 8 + g]);
                uint32_t b1 = __float_as_uint(VK[(kc * 8 + q + 4) * KSTR + nb * 8 + g]);
                mma8(oacc[nb], pa[kc][0], pa[kc][1], pa[kc][2], pa[kc][3], b0, b1);
            }
        }
    }

    // ---- epilogue: normalize; row t==0 forced to zeros ----
    const float inv0 = (srow0 == 0) ? 0.f : 1.f / l0;
    const float inv1 = 1.f / l1;
    float* o0 = out + ((size_t)b * NT + srow0) * NU;
    float* o1 = out + ((size_t)b * NT + srow1) * NU;
    #pragma unroll
    for (int nb = 0; nb < 32; nb++){
        int c = nb * 8 + 2 * q;
        float2 v0, v1;
        v0.x = oacc[nb][0] * inv0; v0.y = oacc[nb][1] * inv0;
        v1.x = oacc[nb][2] * inv1; v1.y = oacc[nb][3] * inv1;
        *(float2*)&o0[c] = v0;
        *(float2*)&o1[c] = v1;
    }
}

// ---------------------------------------------------------------------------
extern "C" void kernel_launch(void* const* d_in, const int* in_sizes, int n_in,
                              void* d_out, int out_size)
{
    const float* x  = (const float*)d_in[0];
    const float* Wq = (const float*)d_in[1];
    const float* Wv = (const float*)d_in[2];
    const float* Wk = (const float*)d_in[3];
    float* out = (float*)d_out;

    const int smem1 = (128 * XSTR + 128 * WSTR) * 4;   // 202,752 B
    const int smem2 = (128 * QSTR + 64 * KSTR) * 4;    // 200,704 B
    cudaFuncSetAttribute(proj_kernel, cudaFuncAttributeMaxDynamicSharedMemorySize, smem1);
    cudaFuncSetAttribute(attn_kernel, cudaFuncAttributeMaxDynamicSharedMemorySize, smem2);

    proj_kernel<<<dim3(NBT / 128, 3), 256, smem1>>>(x, Wq, Wv, Wk);
    attn_kernel<<<dim3(16, 16), 256, smem2>>>(out);
}